// round 9
// baseline (speedup 1.0000x reference)
#include <cuda_runtime.h>
#include <math_constants.h>

// Problem constants (fixed by the reference: B=8, N=4096, D=2)
#define BQ       8
#define NPTS     4096
#define THREADS  512                 // 4 groups x 128
#define GROUP_T  128
#define NGROUPS  4
#define TILE     512                 // queries per block (each thread: 4, stride 128)
#define QPT      4
#define NTILES   (NPTS / TILE)       // 8
#define NBLOCKS  (NTILES * BQ * 2)   // 128
#define REFS_PER_GROUP 1024          // each group scans 1/4 of the reference set
#define CHUNK_QUADS    128           // ref-quads staged per chunk (512 refs)
#define NCHUNK   (REFS_PER_GROUP / (4 * CHUNK_QUADS))  // 2

__device__ float g_partials[NBLOCKS];
__device__ int   g_counter = 0;      // reset by last block each call (graph-replay safe)

// ---- packed f32x2 helpers (SASS FFMA2; ptxas won't emit from C++) ----
__device__ __forceinline__ unsigned long long fma2(unsigned long long a,
                                                   unsigned long long b,
                                                   unsigned long long c) {
    unsigned long long d;
    asm("fma.rn.f32x2 %0, %1, %2, %3;" : "=l"(d) : "l"(a), "l"(b), "l"(c));
    return d;
}
__device__ __forceinline__ unsigned long long pk2(float lo, float hi) {
    unsigned long long r;
    asm("mov.b64 %0, {%1, %2};" : "=l"(r) : "f"(lo), "f"(hi));
    return r;
}
// Register-pair split (ptxas aliases the halves; no SASS MOV expected).
__device__ __forceinline__ void unpk2(unsigned long long v, float& lo, float& hi) {
    asm("mov.b64 {%0, %1}, %2;" : "=f"(lo), "=f"(hi) : "l"(v));
}

// One block: (tile of 512 query points) x (batch) x (direction).
// dir 0: queries = y_true, reference set = y_pred  (also fuses EMD terms)
// dir 1: queries = y_pred, reference set = y_true
// Group g (threads g*128..g*128+127) scans reference range [g*1024, g*1024+1024).
__global__ __launch_bounds__(THREADS, 1)
void chamfer_kernel(const float* __restrict__ yt, const float* __restrict__ yp,
                    float* __restrict__ out) {
    // Per group staging: ref-quads as X=(px0..3), Y=(py0..3), P=(pp0..3)
    __shared__ float4 sX[NGROUPS][CHUNK_QUADS];   // 8 KB
    __shared__ float4 sY[NGROUPS][CHUNK_QUADS];   // 8 KB
    __shared__ float4 sP[NGROUPS][CHUNK_QUADS];   // 8 KB
    __shared__ float  sBest[NGROUPS][TILE];       // 8 KB  per-group per-query best
    __shared__ float  red[THREADS];               // 2 KB
    __shared__ bool   isLast;

    const int tid = threadIdx.x;
    const int g   = tid >> 7;        // group id (0..3)
    const int l   = tid & 127;       // lane within group
    const int b   = blockIdx.y;
    const int dir = blockIdx.z;
    const float* srcBase = (dir == 0 ? yt : yp) + (size_t)b * NPTS * 2; // queries
    const float* refBase = (dir == 0 ? yp : yt) + (size_t)b * NPTS * 2; // reference set

    const int iBase = blockIdx.x * TILE + l;      // queries: iBase + k*128, k=0..3

    // Load this thread's 4 query points; duplicate constants into f32x2 lanes.
    unsigned long long ax2[QPT], ay2[QPT];
    float xx[QPT];
#pragma unroll
    for (int k = 0; k < QPT; k++) {
        const float2 qv = reinterpret_cast<const float2*>(srcBase)[iBase + k * GROUP_T];
        ax2[k] = pk2(-2.0f * qv.x, -2.0f * qv.x);
        ay2[k] = pk2(-2.0f * qv.y, -2.0f * qv.y);
        xx[k]  = fmaf(qv.x, qv.x, qv.y * qv.y);
    }
    // 4 independent min accumulators per query (one per ref lane of the quad).
    float acc[QPT][4];
#pragma unroll
    for (int k = 0; k < QPT; k++)
#pragma unroll
        for (int a = 0; a < 4; a++) acc[k][a] = CUDART_INF_F;

    for (int c = 0; c < NCHUNK; c++) {
        __syncthreads();
        // Stage this group's chunk: 128 quads; thread l stages quad l (2 float4 reads).
        {
            const float4* f4 = reinterpret_cast<const float4*>(refBase)
                             + g * (REFS_PER_GROUP / 2) + c * (CHUNK_QUADS * 2);
            const float4 v0 = f4[2 * l];       // (p0x,p0y,p1x,p1y)
            const float4 v1 = f4[2 * l + 1];   // (p2x,p2y,p3x,p3y)
            sX[g][l] = make_float4(v0.x, v0.z, v1.x, v1.z);
            sY[g][l] = make_float4(v0.y, v0.w, v1.y, v1.w);
            sP[g][l] = make_float4(fmaf(v0.x, v0.x, v0.y * v0.y),
                                   fmaf(v0.z, v0.z, v0.w * v0.w),
                                   fmaf(v1.x, v1.x, v1.y * v1.y),
                                   fmaf(v1.z, v1.z, v1.w * v1.w));
        }
        __syncthreads();

        const ulonglong2* Xp = reinterpret_cast<const ulonglong2*>(sX[g]);
        const ulonglong2* Yp = reinterpret_cast<const ulonglong2*>(sY[g]);
        const ulonglong2* Pp = reinterpret_cast<const ulonglong2*>(sP[g]);
#pragma unroll 4
        for (int j = 0; j < CHUNK_QUADS; j++) {
            const ulonglong2 X = Xp[j];   // (px0,px1),(px2,px3)   LDS.128 broadcast
            const ulonglong2 Y = Yp[j];   // (py0,py1),(py2,py3)
            const ulonglong2 P = Pp[j];   // (pp0,pp1),(pp2,pp3)
#pragma unroll
            for (int k = 0; k < QPT; k++) {
                unsigned long long t01 = fma2(ax2[k], X.x, P.x);
                t01 = fma2(ay2[k], Y.x, t01);
                unsigned long long t23 = fma2(ax2[k], X.y, P.y);
                t23 = fma2(ay2[k], Y.y, t23);
                float t0, t1, t2, t3;
                unpk2(t01, t0, t1);
                unpk2(t23, t2, t3);
                acc[k][0] = fminf(acc[k][0], t0);
                acc[k][1] = fminf(acc[k][1], t1);
                acc[k][2] = fminf(acc[k][2], t2);
                acc[k][3] = fminf(acc[k][3], t3);
            }
        }
    }

    // Collapse accumulators; publish per-group bests.
#pragma unroll
    for (int k = 0; k < QPT; k++)
        sBest[g][l + k * GROUP_T] = fminf(fminf(acc[k][0], acc[k][1]),
                                          fminf(acc[k][2], acc[k][3]));
    __syncthreads();

    // Group 0 combines across groups and forms the final per-query terms.
    float local = 0.0f;
    if (g == 0) {
#pragma unroll
        for (int k = 0; k < QPT; k++) {
            const int s = l + k * GROUP_T;
            const float m = fminf(fminf(sBest[0][s], sBest[1][s]),
                                  fminf(sBest[2][s], sBest[3][s]));
            // NN squared distance: max(xx + best, 0); clamp commutes with min.
            local += fmaxf(xx[k] + m, 0.0f);
        }
        local *= (1.0f / BQ);   // mean over batch of per-batch sums

        if (dir == 0) {
            // Fused EMD: cumsum over D=2 -> (t0-p0)^2 + (t0+t1-p0-p1)^2
            const float* tb = yt + (size_t)b * NPTS * 2;
            const float* pb = yp + (size_t)b * NPTS * 2;
            float e = 0.0f;
#pragma unroll
            for (int k = 0; k < QPT; k++) {
                const int i = iBase + k * GROUP_T;
                const float2 t = reinterpret_cast<const float2*>(tb)[i];
                const float2 p = reinterpret_cast<const float2*>(pb)[i];
                const float d0 = t.x - p.x;
                const float d1 = (t.x + t.y) - (p.x + p.y);
                e = fmaf(d0, d0, e);
                e = fmaf(d1, d1, e);
            }
            local += e * (1.0f / ((float)BQ * NPTS * 2));
        }
    }

    // Deterministic block tree reduction over all 512 threads.
    red[tid] = local;
    __syncthreads();
    for (int s = THREADS / 2; s > 0; s >>= 1) {
        if (tid < s) red[tid] += red[tid + s];
        __syncthreads();
    }
    const int bid = (blockIdx.z * gridDim.y + blockIdx.y) * gridDim.x + blockIdx.x;
    if (tid == 0) {
        g_partials[bid] = red[0];
        __threadfence();
        const int c = atomicAdd(&g_counter, 1);
        isLast = (c == NBLOCKS - 1);
    }
    __syncthreads();

    // Last block: deterministic fixed-order final sum of the 128 partials.
    if (isLast) {
        float v = 0.0f;
        if (tid < NBLOCKS) {
            __threadfence();
            v = *((volatile float*)&g_partials[tid]);
        }
        red[tid] = v;
        __syncthreads();
        for (int s = THREADS / 2; s > 0; s >>= 1) {
            if (tid < s) red[tid] += red[tid + s];
            __syncthreads();
        }
        if (tid == 0) {
            out[0] = red[0];
            g_counter = 0;   // reset for next graph replay
        }
    }
}

extern "C" void kernel_launch(void* const* d_in, const int* in_sizes, int n_in,
                              void* d_out, int out_size) {
    const float* y_true = (const float*)d_in[0];
    const float* y_pred = (const float*)d_in[1];
    float* out = (float*)d_out;

    dim3 grid(NTILES, BQ, 2);
    chamfer_kernel<<<grid, THREADS>>>(y_true, y_pred, out);
}